// round 2
// baseline (speedup 1.0000x reference)
#include <cuda_runtime.h>

// OHEM cross-entropy on GB300.
// Shapes: input (16,19,512,512) f32, target (16,512,512) int32 (JAX demotes
// int64 -> int32 with x64 disabled), out: scalar f32.
#define CCH   19
#define HW    262144           // 512*512
#define BATCH 16
#define BHW   (BATCH*HW)       // 4,194,304
#define NMIN  262144
#define THRESH 0.35667494f     // -log(0.7) in f32
#define NBINS 65536
#define NPART 32

// Scratch (statically allocated — no cudaMalloc anywhere).
__device__ float              g_loss[BHW];       // per-pixel loss (0 for ignore)
__device__ unsigned int       g_hist_cnt[NBINS]; // fallback top-k histogram
__device__ float              g_hist_sum[NBINS];
__device__ double             g_part_sum[NPART]; // striped partials (sum of loss>THRESH)
__device__ unsigned long long g_part_cnt[NPART]; // striped partials (count loss>THRESH)
__device__ int                g_flag;            // 1 => cond-true branch already wrote out

// ---------------------------------------------------------------------------
// Reset accumulators each replay (graph-captured, so must be explicit work).
__global__ void init_k() {
    int i = blockIdx.x * blockDim.x + threadIdx.x;
    if (i < NBINS) { g_hist_cnt[i] = 0u; g_hist_sum[i] = 0.0f; }
    if (i < NPART) { g_part_sum[i] = 0.0; g_part_cnt[i] = 0ull; }
    if (i == 0)    { g_flag = 0; }
}

// ---------------------------------------------------------------------------
// Main pass: per-pixel CE loss + thresholded count/sum reduction + loss store.
__global__ __launch_bounds__(256) void ce_k(const float* __restrict__ x,
                                            const int* __restrict__ tgt) {
    int p = blockIdx.x * 256 + threadIdx.x;   // exact grid: BHW/256 blocks
    int b = p >> 18;                           // HW = 2^18
    int s = p & (HW - 1);
    const float* xp = x + (size_t)b * (size_t)(CCH * HW) + (size_t)s;

    int t = tgt[p];

    // Load all 19 channel logits for this pixel (coalesced per channel plane).
    float v[CCH];
    #pragma unroll
    for (int c = 0; c < CCH; c++) v[c] = __ldg(xp + (size_t)c * HW);

    float m = v[0];
    #pragma unroll
    for (int c = 1; c < CCH; c++) m = fmaxf(m, v[c]);

    float se = 0.0f;
    float xt = v[0];
    #pragma unroll
    for (int c = 0; c < CCH; c++) {
        se += __expf(v[c] - m);
        if (c == t) xt = v[c];
    }

    // loss = -(x_t - m - log(sum exp(x_c - m))); 0 if ignore_index
    float loss = (t == 255) ? 0.0f : (m - xt + __logf(se));
    g_loss[p] = loss;

    // Reduce: count and sum of losses strictly above THRESH.
    bool gt = loss > THRESH;
    float        sv = gt ? loss : 0.0f;
    unsigned int cv = gt ? 1u : 0u;

    #pragma unroll
    for (int o = 16; o > 0; o >>= 1) {
        sv += __shfl_down_sync(0xffffffffu, sv, o);
        cv += __shfl_down_sync(0xffffffffu, cv, o);
    }
    __shared__ float    ss[8];
    __shared__ unsigned sc[8];
    int lane = threadIdx.x & 31, w = threadIdx.x >> 5;
    if (lane == 0) { ss[w] = sv; sc[w] = cv; }
    __syncthreads();
    if (w == 0) {
        float    s2 = (lane < 8) ? ss[lane] : 0.0f;
        unsigned c2 = (lane < 8) ? sc[lane] : 0u;
        #pragma unroll
        for (int o = 4; o > 0; o >>= 1) {
            s2 += __shfl_down_sync(0xffffffffu, s2, o);
            c2 += __shfl_down_sync(0xffffffffu, c2, o);
        }
        if (lane == 0) {
            int slot = blockIdx.x & (NPART - 1);   // stripe atomics over 32 addrs
            atomicAdd(&g_part_sum[slot], (double)s2);
            atomicAdd(&g_part_cnt[slot], (unsigned long long)c2);
        }
    }
}

// ---------------------------------------------------------------------------
// If count(loss>THRESH) > NMIN: answer = sum/count (this is the branch the
// bench data takes). Otherwise set flag=0 and let the fallback kernels run.
__global__ void finalize_k(float* out) {
    double s = 0.0;
    unsigned long long c = 0ull;
    for (int i = 0; i < NPART; i++) { s += g_part_sum[i]; c += g_part_cnt[i]; }
    if (c > (unsigned long long)NMIN) {
        out[0] = (float)(s / (double)c);
        g_flag = 1;
    } else {
        g_flag = 0;
    }
}

// ---------------------------------------------------------------------------
// Fallback path (top-NMIN sum): histogram over float bits (monotone for >=0).
__global__ void hist_k() {
    if (g_flag) return;   // cond-true branch: early exit (cheap null pass)
    int stride = gridDim.x * blockDim.x;
    for (int p = blockIdx.x * blockDim.x + threadIdx.x; p < BHW; p += stride) {
        float l = g_loss[p];
        unsigned bits = __float_as_uint(l);
        unsigned bin  = bits >> 16;        // loss >= 0 so bin < 32768
        if (bin >= NBINS) bin = NBINS - 1; // safety clamp
        atomicAdd(&g_hist_cnt[bin], 1u);
        atomicAdd(&g_hist_sum[bin], l);
    }
}

__global__ void select_k(float* out) {
    if (g_flag) return;
    __shared__ unsigned long long scnt[256];
    __shared__ double             ssum[256];
    int t = threadIdx.x;
    // chunk t covers reversed bins [t*256, (t+1)*256): scan from largest values
    unsigned long long c = 0ull;
    double             s = 0.0;
    for (int j = 0; j < 256; j++) {
        int bin = NBINS - 1 - (t * 256 + j);
        c += g_hist_cnt[bin];
        s += (double)g_hist_sum[bin];
    }
    scnt[t] = c; ssum[t] = s;
    __syncthreads();
    if (t == 0) {
        unsigned long long cum = 0ull;
        double             sum = 0.0;
        int chunk = 0;
        for (chunk = 0; chunk < 256; chunk++) {
            if (cum + scnt[chunk] >= (unsigned long long)NMIN) break;
            cum += scnt[chunk];
            sum += ssum[chunk];
        }
        double result;
        if (chunk == 256) {
            // fewer than NMIN elements total (cannot happen here: BHW >= NMIN)
            result = (cum > 0) ? (sum / (double)cum) : 0.0;
        } else {
            for (int j = 0; j < 256; j++) {
                int bin = NBINS - 1 - (chunk * 256 + j);
                unsigned long long bc = g_hist_cnt[bin];
                double             bs = (double)g_hist_sum[bin];
                if (cum + bc >= (unsigned long long)NMIN) {
                    unsigned long long rem = (unsigned long long)NMIN - cum;
                    double avg = bc ? (bs / (double)bc) : 0.0;
                    sum += avg * (double)rem;   // within-bin tie approximation
                    break;
                }
                cum += bc;
                sum += bs;
            }
            result = sum / (double)NMIN;
        }
        out[0] = (float)result;
    }
}

// ---------------------------------------------------------------------------
extern "C" void kernel_launch(void* const* d_in, const int* in_sizes, int n_in,
                              void* d_out, int out_size) {
    // Identify operands by size (input has 19x the elements of target).
    const float* x;
    const int*   tg;
    if (in_sizes[0] >= in_sizes[1]) {
        x  = (const float*)d_in[0];
        tg = (const int*)d_in[1];
    } else {
        x  = (const float*)d_in[1];
        tg = (const int*)d_in[0];
    }
    float* out = (float*)d_out;

    init_k<<<(NBINS + 255) / 256, 256>>>();
    ce_k<<<BHW / 256, 256>>>(x, tg);
    finalize_k<<<1, 1>>>(out);
    hist_k<<<2048, 256>>>();
    select_k<<<1, 256>>>(out);
}